// round 1
// baseline (speedup 1.0000x reference)
#include <cuda_runtime.h>

// MidGCN restructured:
//   DAD@M      = d_row ⊙ (adj @ (d_col ⊙ M))
//   adj_f @ M  = α·M + (α−1)·DAD@M − DAD@(DAD@M)
// avoids the 8192^3 materialization of adj_f entirely.

#define NN 8192
#define NF 512
#define NH 256
#define FALPHA 0.5f

// ---- scratch (static __device__ globals; no allocation allowed) ----
__device__ float g_rowsum[NN];
__device__ float g_colsum[NN];
__device__ float g_drow[NN];
__device__ float g_dcol[NN];
__device__ float g_XW1[NN * NH];
__device__ float g_T1[NN * NH];
__device__ float g_T2[NN * NH];
__device__ float g_G[NN * 2];
__device__ float g_S1[NN * 2];
__device__ float g_S2[NN * 2];

// ---- degree sums ----
__global__ void k_zero() {
    int i = blockIdx.x * blockDim.x + threadIdx.x;
    if (i < NN) g_colsum[i] = 0.f;
}

__global__ void k_rowsum(const float* __restrict__ adj) {
    int row  = blockIdx.x * 8 + (threadIdx.x >> 5);
    int lane = threadIdx.x & 31;
    const float4* a = (const float4*)(adj + (size_t)row * NN);
    float s = 0.f;
#pragma unroll 4
    for (int it = lane; it < NN / 4; it += 32) {
        float4 v = a[it];
        s += (v.x + v.y) + (v.z + v.w);
    }
#pragma unroll
    for (int o = 16; o; o >>= 1) s += __shfl_xor_sync(0xffffffffu, s, o);
    if (!lane) g_rowsum[row] = s;
}

__global__ void k_colsum(const float* __restrict__ adj) {
    int col = blockIdx.x * 256 + threadIdx.x;
    const float* p = adj + (size_t)blockIdx.y * 128 * NN + col;
    float s = 0.f;
#pragma unroll 8
    for (int r = 0; r < 128; r++) s += p[(size_t)r * NN];
    atomicAdd(&g_colsum[col], s);
}

__global__ void k_finalize() {
    int i = blockIdx.x * blockDim.x + threadIdx.x;
    if (i >= NN) return;
    float rs = g_rowsum[i];
    g_drow[i] = rs > 0.f ? rsqrtf(rs) : 0.f;
    float cs = g_colsum[i];
    g_dcol[i] = cs > 0.f ? rsqrtf(cs) : 0.f;
}

// ---- generic M x K @ K x 256 GEMM (M = 8192 rows of A) ----
// SCALE=1: B rows pre-scaled by g_dcol[k], C rows post-scaled by g_drow[row]
// BM=128, BN=128, BK=16, 256 threads, 8x8 register tile per thread.
__global__ __launch_bounds__(256) void k_gemm(const float* __restrict__ A,
                                              const float* __restrict__ Bm,
                                              float* __restrict__ C,
                                              int K, int SCALE) {
    __shared__ float As[16][132];   // padded: 132 % 4 == 0 keeps LDS.128 legal
    __shared__ float Bs[16][128];

    int tid = threadIdx.x;
    int tx = tid & 15;       // 0..15 -> col group of 8
    int ty = tid >> 4;       // 0..15 -> row group of 8

    const float* Abase = A + (size_t)(blockIdx.y * 128) * K;

    float acc[8][8];
#pragma unroll
    for (int i = 0; i < 8; i++)
#pragma unroll
        for (int j = 0; j < 8; j++) acc[i][j] = 0.f;

    int ar = tid >> 2;          // 0..63
    int ac = (tid & 3) * 4;     // 0,4,8,12
    int br = tid >> 5;          // 0..7
    int bc = (tid & 31) * 4;    // 0..124

    for (int k0 = 0; k0 < K; k0 += 16) {
        // A tile: 128x16, 2 float4 per thread, stored transposed
#pragma unroll
        for (int l = 0; l < 2; l++) {
            int r = ar + l * 64;
            float4 v = *(const float4*)(Abase + (size_t)r * K + (k0 + ac));
            As[ac + 0][r] = v.x; As[ac + 1][r] = v.y;
            As[ac + 2][r] = v.z; As[ac + 3][r] = v.w;
        }
        // B tile: 16x128, 2 float4 per thread, d_col prescale fused
#pragma unroll
        for (int l = 0; l < 2; l++) {
            int r = br + l * 8;
            float4 v = *(const float4*)(Bm + (size_t)(k0 + r) * NH + blockIdx.x * 128 + bc);
            if (SCALE) {
                float sc = g_dcol[k0 + r];
                v.x *= sc; v.y *= sc; v.z *= sc; v.w *= sc;
            }
            *(float4*)&Bs[r][bc] = v;
        }
        __syncthreads();

#pragma unroll
        for (int k = 0; k < 16; k++) {
            float4 a0 = *(const float4*)&As[k][ty * 8];
            float4 a1 = *(const float4*)&As[k][ty * 8 + 4];
            float4 b0 = *(const float4*)&Bs[k][tx * 8];
            float4 b1 = *(const float4*)&Bs[k][tx * 8 + 4];
            float av[8] = {a0.x, a0.y, a0.z, a0.w, a1.x, a1.y, a1.z, a1.w};
            float bv[8] = {b0.x, b0.y, b0.z, b0.w, b1.x, b1.y, b1.z, b1.w};
#pragma unroll
            for (int i = 0; i < 8; i++)
#pragma unroll
                for (int j = 0; j < 8; j++)
                    acc[i][j] = fmaf(av[i], bv[j], acc[i][j]);
        }
        __syncthreads();
    }

#pragma unroll
    for (int i = 0; i < 8; i++) {
        int row = blockIdx.y * 128 + ty * 8 + i;
        float sc = SCALE ? g_drow[row] : 1.f;
        float* cp = C + (size_t)row * NH + blockIdx.x * 128 + tx * 8;
        float4 v0 = make_float4(acc[i][0] * sc, acc[i][1] * sc, acc[i][2] * sc, acc[i][3] * sc);
        float4 v1 = make_float4(acc[i][4] * sc, acc[i][5] * sc, acc[i][6] * sc, acc[i][7] * sc);
        *(float4*)cp = v0;
        *(float4*)(cp + 4) = v1;
    }
}

// ---- fused: H = relu(alpha*XW1 + (alpha-1)*T1 - T2); G = H @ W2 ----
__global__ void k_hidden(const float* __restrict__ W2) {
    int row  = blockIdx.x * 8 + (threadIdx.x >> 5);
    int lane = threadIdx.x & 31;
    float g0 = 0.f, g1 = 0.f;
    const float* xw = g_XW1 + (size_t)row * NH;
    const float* t1 = g_T1 + (size_t)row * NH;
    const float* t2 = g_T2 + (size_t)row * NH;
#pragma unroll
    for (int j = lane; j < NH; j += 32) {
        float p = FALPHA * xw[j] + (FALPHA - 1.f) * t1[j] - t2[j];
        float h = fmaxf(p, 0.f);
        g0 = fmaf(h, __ldg(&W2[j * 2 + 0]), g0);
        g1 = fmaf(h, __ldg(&W2[j * 2 + 1]), g1);
    }
#pragma unroll
    for (int o = 16; o; o >>= 1) {
        g0 += __shfl_xor_sync(0xffffffffu, g0, o);
        g1 += __shfl_xor_sync(0xffffffffu, g1, o);
    }
    if (!lane) {
        g_G[row * 2 + 0] = g0;
        g_G[row * 2 + 1] = g1;
    }
}

// ---- narrow DAD apply: Sdst = d_row ⊙ (adj @ (d_col ⊙ Bsrc)), Bsrc 8192x2 ----
// full (d_col ⊙ B) vector cached in 64 KB dynamic smem; memory-bound on adj.
__global__ void k_narrow(const float* __restrict__ adj,
                         const float* __restrict__ Bsrc,
                         float* __restrict__ Sdst) {
    extern __shared__ float2 sB[];
    int tid = threadIdx.x;
    for (int k = tid; k < NN; k += 256) {
        float sc = g_dcol[k];
        sB[k] = make_float2(sc * Bsrc[k * 2], sc * Bsrc[k * 2 + 1]);
    }
    __syncthreads();

    int row  = blockIdx.x * 8 + (tid >> 5);
    int lane = tid & 31;
    const float4* a = (const float4*)(adj + (size_t)row * NN);
    float s0 = 0.f, s1 = 0.f;
#pragma unroll 4
    for (int it = lane; it < NN / 4; it += 32) {
        float4 v = a[it];
        int k = it * 4;
        float2 b0 = sB[k], b1 = sB[k + 1], b2 = sB[k + 2], b3 = sB[k + 3];
        s0 += v.x * b0.x + v.y * b1.x + v.z * b2.x + v.w * b3.x;
        s1 += v.x * b0.y + v.y * b1.y + v.z * b2.y + v.w * b3.y;
    }
#pragma unroll
    for (int o = 16; o; o >>= 1) {
        s0 += __shfl_xor_sync(0xffffffffu, s0, o);
        s1 += __shfl_xor_sync(0xffffffffu, s1, o);
    }
    if (!lane) {
        float sc = g_drow[row];
        Sdst[row * 2 + 0] = sc * s0;
        Sdst[row * 2 + 1] = sc * s1;
    }
}

// ---- final: out = log_softmax(alpha*G + (alpha-1)*S1 - S2 + b2) ----
__global__ void k_final(const float* __restrict__ b2, float* __restrict__ out) {
    int i = blockIdx.x * blockDim.x + threadIdx.x;
    if (i >= NN) return;
    float o0 = FALPHA * g_G[i * 2 + 0] + (FALPHA - 1.f) * g_S1[i * 2 + 0] - g_S2[i * 2 + 0] + b2[0];
    float o1 = FALPHA * g_G[i * 2 + 1] + (FALPHA - 1.f) * g_S1[i * 2 + 1] - g_S2[i * 2 + 1] + b2[1];
    float m = fmaxf(o0, o1);
    float lse = m + logf(expf(o0 - m) + expf(o1 - m));
    out[i * 2 + 0] = o0 - lse;
    out[i * 2 + 1] = o1 - lse;
}

extern "C" void kernel_launch(void* const* d_in, const int* in_sizes, int n_in,
                              void* d_out, int out_size) {
    const float* x   = (const float*)d_in[0];
    const float* adj = (const float*)d_in[1];
    const float* W1  = (const float*)d_in[2];
    const float* W2  = (const float*)d_in[3];
    const float* b2  = (const float*)d_in[4];
    float* out = (float*)d_out;

    (void)in_sizes; (void)n_in; (void)out_size;

    // resolve device symbol addresses for kernels that take scratch pointers
    float *pXW1, *pT1, *pT2, *pG, *pS1, *pS2;
    cudaGetSymbolAddress((void**)&pXW1, g_XW1);
    cudaGetSymbolAddress((void**)&pT1, g_T1);
    cudaGetSymbolAddress((void**)&pT2, g_T2);
    cudaGetSymbolAddress((void**)&pG, g_G);
    cudaGetSymbolAddress((void**)&pS1, g_S1);
    cudaGetSymbolAddress((void**)&pS2, g_S2);

    cudaFuncSetAttribute(k_narrow, cudaFuncAttributeMaxDynamicSharedMemorySize, 65536);

    // degree vectors
    k_zero<<<NN / 256, 256>>>();
    k_rowsum<<<NN / 8, 256>>>(adj);
    k_colsum<<<dim3(NN / 256, NN / 128), 256>>>(adj);
    k_finalize<<<NN / 256, 256>>>();

    // XW1 = x @ W1
    k_gemm<<<dim3(2, 64), 256>>>(x, W1, pXW1, NF, 0);

    // T1 = DAD @ XW1 ; T2 = DAD @ T1   (the two dominant GEMMs)
    k_gemm<<<dim3(2, 64), 256>>>(adj, pXW1, pT1, NN, 1);
    k_gemm<<<dim3(2, 64), 256>>>(adj, pT1, pT2, NN, 1);

    // H = relu(adj_f @ XW1), G = H @ W2 (fused)
    k_hidden<<<NN / 8, 256>>>(W2);

    // S1 = DAD @ G ; S2 = DAD @ S1
    k_narrow<<<NN / 8, 256, 65536>>>(adj, pG, pS1);
    k_narrow<<<NN / 8, 256, 65536>>>(adj, pS1, pS2);

    // out = log_softmax(alpha*G + (alpha-1)*S1 - S2 + b2)
    k_final<<<NN / 256, 256>>>(b2, out);
}

// round 2
// speedup vs baseline: 3.4566x; 3.4566x over previous
#include <cuda_runtime.h>

// MidGCN restructured:
//   DAD@M      = d_row ⊙ (adj @ (d_col ⊙ M))
//   adj_f @ M  = α·M + (α−1)·DAD@M − DAD@(DAD@M)
// Big GEMMs on tensor cores (mma.sync tf32), scales fused into epilogues.

#define NN 8192
#define NF 512
#define NH 256
#define FALPHA 0.5f

// ---- scratch ----
__device__ float g_rowsum[NN];
__device__ float g_colsum[NN];
__device__ float g_drow[NN];
__device__ float g_dcol[NN];
__device__ float g_W1t[NF * NH];   // rna(W1)
__device__ float g_XW1[NN * NH];   // x @ W1
__device__ float g_Bs1[NN * NH];   // rna(dcol ⊙ XW1)          (B for T1 gemm)
__device__ float g_T1[NN * NH];    // DAD @ XW1
__device__ float g_Bs2[NN * NH];   // rna(dcol ⊙ T1)           (B for T2 gemm)
__device__ float g_T2[NN * NH];    // DAD @ T1
__device__ float g_G[NN * 2];
__device__ float g_S1[NN * 2];
__device__ float g_S2[NN * 2];

// ================= degree sums =================
__global__ void k_zero() {
    int i = blockIdx.x * blockDim.x + threadIdx.x;
    if (i < NN) g_colsum[i] = 0.f;
}

__global__ void k_rowsum(const float* __restrict__ adj) {
    int row  = blockIdx.x * 8 + (threadIdx.x >> 5);
    int lane = threadIdx.x & 31;
    const float4* a = (const float4*)(adj + (size_t)row * NN);
    float s = 0.f;
#pragma unroll 4
    for (int it = lane; it < NN / 4; it += 32) {
        float4 v = a[it];
        s += (v.x + v.y) + (v.z + v.w);
    }
#pragma unroll
    for (int o = 16; o; o >>= 1) s += __shfl_xor_sync(0xffffffffu, s, o);
    if (!lane) g_rowsum[row] = s;
}

__global__ void k_colsum(const float* __restrict__ adj) {
    int col = blockIdx.x * 256 + threadIdx.x;
    const float* p = adj + (size_t)blockIdx.y * 128 * NN + col;
    float s = 0.f;
#pragma unroll 8
    for (int r = 0; r < 128; r++) s += p[(size_t)r * NN];
    atomicAdd(&g_colsum[col], s);
}

__global__ void k_finalize() {
    int i = blockIdx.x * blockDim.x + threadIdx.x;
    if (i >= NN) return;
    float rs = g_rowsum[i];
    g_drow[i] = rs > 0.f ? rsqrtf(rs) : 0.f;
    float cs = g_colsum[i];
    g_dcol[i] = cs > 0.f ? rsqrtf(cs) : 0.f;
}

// round W1 to tf32 grid (so the mma B operand is exactly representable)
__device__ __forceinline__ unsigned f2tf(float f) {
    unsigned r;
    asm("cvt.rna.tf32.f32 %0, %1;" : "=r"(r) : "f"(f));
    return r;
}

__global__ void k_roundW1(const float* __restrict__ W1) {
    int i = blockIdx.x * blockDim.x + threadIdx.x;
    if (i < NF * NH) g_W1t[i] = __uint_as_float(f2tf(W1[i]));
}

// ================= tf32 tensor-core GEMM =================
// C[8192 x 256 tile] = A[8192 x K] @ B[K x 256], BM=BN=128, BK=32, 256 thr.
// SCALE: postscale rows of C by g_drow. AUX: also emit rna(g_dcol[row] * C).
#define SA 36    // A smem row stride (floats): banks 4m+k -> conflict-free
#define SB 136   // B smem row stride (floats): banks 8k+n -> conflict-free

__device__ __forceinline__ void cp16(void* smem, const void* gmem) {
    unsigned s = (unsigned)__cvta_generic_to_shared(smem);
    asm volatile("cp.async.cg.shared.global [%0], [%1], 16;\n" :: "r"(s), "l"(gmem));
}

__global__ __launch_bounds__(256) void k_mma(const float* __restrict__ A,
                                             const float* __restrict__ B,
                                             float* __restrict__ C,
                                             float* __restrict__ Caux,
                                             int K, int SCALE, int AUX) {
    extern __shared__ float sm[];
    float* As = sm;                    // [2][128][SA]
    float* Bs = sm + 2 * 128 * SA;     // [2][32][SB]

    const int tid  = threadIdx.x;
    const int wid  = tid >> 5, lane = tid & 31;
    const int g    = lane >> 2, t = lane & 3;
    const int wm   = (wid & 1) * 64;       // warp row offset in block tile
    const int wn   = (wid >> 1) * 32;      // warp col offset
    const int bm   = blockIdx.y * 128;
    const int bn   = blockIdx.x * 128;

    float acc[4][4][4];
#pragma unroll
    for (int i = 0; i < 4; i++)
#pragma unroll
        for (int j = 0; j < 4; j++)
#pragma unroll
            for (int r = 0; r < 4; r++) acc[i][j][r] = 0.f;

    const float* Ab = A + (size_t)bm * K;
    const float* Bb = B + bn;
    const int KT = K / 32;

    // ---- stage 0 loads ----
    {
        float* as = As;
        float* bs = Bs;
#pragma unroll
        for (int p = 0; p < 4; p++) {
            int ch = tid + p * 256;
            int ar = ch >> 3, ac = (ch & 7) * 4;
            cp16(as + ar * SA + ac, Ab + (size_t)ar * K + ac);
            int br = ch >> 5, bc = (ch & 31) * 4;
            cp16(bs + br * SB + bc, Bb + (size_t)br * NH + bc);
        }
        asm volatile("cp.async.commit_group;\n");
    }

    for (int kt = 0; kt < KT; kt++) {
        int buf = kt & 1;
        if (kt + 1 < KT) {
            float* as = As + (buf ^ 1) * 128 * SA;
            float* bs = Bs + (buf ^ 1) * 32 * SB;
            int k0 = (kt + 1) * 32;
#pragma unroll
            for (int p = 0; p < 4; p++) {
                int ch = tid + p * 256;
                int ar = ch >> 3, ac = (ch & 7) * 4;
                cp16(as + ar * SA + ac, Ab + (size_t)ar * K + k0 + ac);
                int br = ch >> 5, bc = (ch & 31) * 4;
                cp16(bs + br * SB + bc, Bb + (size_t)(k0 + br) * NH + bc);
            }
            asm volatile("cp.async.commit_group;\n");
            asm volatile("cp.async.wait_group 1;\n");
        } else {
            asm volatile("cp.async.wait_group 0;\n");
        }
        __syncthreads();

        const float* as = As + buf * 128 * SA;
        const float* bs = Bs + buf * 32 * SB;

#pragma unroll
        for (int ks = 0; ks < 4; ks++) {
            unsigned af[4][4];
#pragma unroll
            for (int mt = 0; mt < 4; mt++) {
                const float* ap = as + (wm + mt * 16 + g) * SA + ks * 8 + t;
                af[mt][0] = f2tf(ap[0]);
                af[mt][1] = f2tf(ap[8 * SA]);
                af[mt][2] = f2tf(ap[4]);
                af[mt][3] = f2tf(ap[8 * SA + 4]);
            }
            unsigned bf[4][2];
#pragma unroll
            for (int nt = 0; nt < 4; nt++) {
                const float* bp = bs + (ks * 8 + t) * SB + wn + nt * 8 + g;
                bf[nt][0] = __float_as_uint(bp[0]);       // B pre-rounded
                bf[nt][1] = __float_as_uint(bp[4 * SB]);
            }
#pragma unroll
            for (int mt = 0; mt < 4; mt++)
#pragma unroll
                for (int nt = 0; nt < 4; nt++) {
                    asm volatile(
                        "mma.sync.aligned.m16n8k8.row.col.f32.tf32.tf32.f32 "
                        "{%0,%1,%2,%3}, {%4,%5,%6,%7}, {%8,%9}, {%0,%1,%2,%3};\n"
                        : "+f"(acc[mt][nt][0]), "+f"(acc[mt][nt][1]),
                          "+f"(acc[mt][nt][2]), "+f"(acc[mt][nt][3])
                        : "r"(af[mt][0]), "r"(af[mt][1]), "r"(af[mt][2]), "r"(af[mt][3]),
                          "r"(bf[nt][0]), "r"(bf[nt][1]));
                }
        }
        __syncthreads();
    }

    // ---- epilogue: C = drow? ⊙ acc ; Caux = rna(dcol ⊙ C) ----
#pragma unroll
    for (int mt = 0; mt < 4; mt++) {
        int r0 = bm + wm + mt * 16 + g;
        int r1 = r0 + 8;
        float s0 = SCALE ? g_drow[r0] : 1.f;
        float s1 = SCALE ? g_drow[r1] : 1.f;
        float d0 = g_dcol[r0], d1 = g_dcol[r1];
#pragma unroll
        for (int nt = 0; nt < 4; nt++) {
            int c = bn + wn + nt * 8 + 2 * t;
            float v0 = acc[mt][nt][0] * s0, v1 = acc[mt][nt][1] * s0;
            float v2 = acc[mt][nt][2] * s1, v3 = acc[mt][nt][3] * s1;
            *(float2*)(C + (size_t)r0 * NH + c) = make_float2(v0, v1);
            *(float2*)(C + (size_t)r1 * NH + c) = make_float2(v2, v3);
            if (AUX) {
                *(float2*)(Caux + (size_t)r0 * NH + c) =
                    make_float2(__uint_as_float(f2tf(d0 * v0)),
                                __uint_as_float(f2tf(d0 * v1)));
                *(float2*)(Caux + (size_t)r1 * NH + c) =
                    make_float2(__uint_as_float(f2tf(d1 * v2)),
                                __uint_as_float(f2tf(d1 * v3)));
            }
        }
    }
}

// ================= fused hidden + output-gemm =================
__global__ void k_hidden(const float* __restrict__ W2) {
    int row  = blockIdx.x * 8 + (threadIdx.x >> 5);
    int lane = threadIdx.x & 31;
    float g0 = 0.f, g1 = 0.f;
    const float* xw = g_XW1 + (size_t)row * NH;
    const float* t1 = g_T1 + (size_t)row * NH;
    const float* t2 = g_T2 + (size_t)row * NH;
#pragma unroll
    for (int j = lane; j < NH; j += 32) {
        float p = FALPHA * xw[j] + (FALPHA - 1.f) * t1[j] - t2[j];
        float h = fmaxf(p, 0.f);
        g0 = fmaf(h, __ldg(&W2[j * 2 + 0]), g0);
        g1 = fmaf(h, __ldg(&W2[j * 2 + 1]), g1);
    }
#pragma unroll
    for (int o = 16; o; o >>= 1) {
        g0 += __shfl_xor_sync(0xffffffffu, g0, o);
        g1 += __shfl_xor_sync(0xffffffffu, g1, o);
    }
    if (!lane) {
        g_G[row * 2 + 0] = g0;
        g_G[row * 2 + 1] = g1;
    }
}

// ================= narrow DAD apply (N=2) =================
__global__ void k_narrow(const float* __restrict__ adj,
                         const float* __restrict__ Bsrc,
                         float* __restrict__ Sdst) {
    extern __shared__ float2 sB[];
    int tid = threadIdx.x;
    for (int k = tid; k < NN; k += 256) {
        float sc = g_dcol[k];
        sB[k] = make_float2(sc * Bsrc[k * 2], sc * Bsrc[k * 2 + 1]);
    }
    __syncthreads();

    int row  = blockIdx.x * 8 + (tid >> 5);
    int lane = tid & 31;
    const float4* a = (const float4*)(adj + (size_t)row * NN);
    float s0 = 0.f, s1 = 0.f;
#pragma unroll 4
    for (int it = lane; it < NN / 4; it += 32) {
        float4 v = a[it];
        int k = it * 4;
        float2 b0 = sB[k], b1 = sB[k + 1], b2 = sB[k + 2], b3 = sB[k + 3];
        s0 += v.x * b0.x + v.y * b1.x + v.z * b2.x + v.w * b3.x;
        s1 += v.x * b0.y + v.y * b1.y + v.z * b2.y + v.w * b3.y;
    }
#pragma unroll
    for (int o = 16; o; o >>= 1) {
        s0 += __shfl_xor_sync(0xffffffffu, s0, o);
        s1 += __shfl_xor_sync(0xffffffffu, s1, o);
    }
    if (!lane) {
        float sc = g_drow[row];
        Sdst[row * 2 + 0] = sc * s0;
        Sdst[row * 2 + 1] = sc * s1;
    }
}

// ================= final log-softmax =================
__global__ void k_final(const float* __restrict__ b2, float* __restrict__ out) {
    int i = blockIdx.x * blockDim.x + threadIdx.x;
    if (i >= NN) return;
    float o0 = FALPHA * g_G[i * 2 + 0] + (FALPHA - 1.f) * g_S1[i * 2 + 0] - g_S2[i * 2 + 0] + b2[0];
    float o1 = FALPHA * g_G[i * 2 + 1] + (FALPHA - 1.f) * g_S1[i * 2 + 1] - g_S2[i * 2 + 1] + b2[1];
    float m = fmaxf(o0, o1);
    float lse = m + logf(expf(o0 - m) + expf(o1 - m));
    out[i * 2 + 0] = o0 - lse;
    out[i * 2 + 1] = o1 - lse;
}

extern "C" void kernel_launch(void* const* d_in, const int* in_sizes, int n_in,
                              void* d_out, int out_size) {
    const float* x   = (const float*)d_in[0];
    const float* adj = (const float*)d_in[1];
    const float* W1  = (const float*)d_in[2];
    const float* W2  = (const float*)d_in[3];
    const float* b2  = (const float*)d_in[4];
    float* out = (float*)d_out;

    (void)in_sizes; (void)n_in; (void)out_size;

    float *pW1t, *pXW1, *pBs1, *pT1, *pBs2, *pT2, *pG, *pS1, *pS2;
    cudaGetSymbolAddress((void**)&pW1t, g_W1t);
    cudaGetSymbolAddress((void**)&pXW1, g_XW1);
    cudaGetSymbolAddress((void**)&pBs1, g_Bs1);
    cudaGetSymbolAddress((void**)&pT1, g_T1);
    cudaGetSymbolAddress((void**)&pBs2, g_Bs2);
    cudaGetSymbolAddress((void**)&pT2, g_T2);
    cudaGetSymbolAddress((void**)&pG, g_G);
    cudaGetSymbolAddress((void**)&pS1, g_S1);
    cudaGetSymbolAddress((void**)&pS2, g_S2);

    const int MMA_SMEM = (2 * 128 * SA + 2 * 32 * SB) * 4;  // 71680 B
    cudaFuncSetAttribute(k_mma, cudaFuncAttributeMaxDynamicSharedMemorySize, MMA_SMEM);
    cudaFuncSetAttribute(k_narrow, cudaFuncAttributeMaxDynamicSharedMemorySize, 65536);

    // degree vectors
    k_zero<<<NN / 256, 256>>>();
    k_rowsum<<<NN / 8, 256>>>(adj);
    k_colsum<<<dim3(NN / 256, NN / 128), 256>>>(adj);
    k_finalize<<<NN / 256, 256>>>();

    // W1 -> tf32 grid
    k_roundW1<<<(NF * NH) / 256, 256>>>(W1);

    // XW1 = x @ W1 ; also emit Bs1 = rna(dcol ⊙ XW1)
    k_mma<<<dim3(2, 64), 256, MMA_SMEM>>>(x, pW1t, pXW1, pBs1, NF, 0, 1);

    // T1 = drow ⊙ (adj @ Bs1) ; also emit Bs2 = rna(dcol ⊙ T1)
    k_mma<<<dim3(2, 64), 256, MMA_SMEM>>>(adj, pBs1, pT1, pBs2, NN, 1, 1);

    // T2 = drow ⊙ (adj @ Bs2)
    k_mma<<<dim3(2, 64), 256, MMA_SMEM>>>(adj, pBs2, pT2, (float*)0, NN, 1, 0);

    // H = relu(adj_f @ XW1), G = H @ W2 (fused)
    k_hidden<<<NN / 8, 256>>>(W2);

    // S1 = DAD @ G ; S2 = DAD @ S1
    k_narrow<<<NN / 8, 256, 65536>>>(adj, pG, pS1);
    k_narrow<<<NN / 8, 256, 65536>>>(adj, pS1, pS2);

    // out = log_softmax(alpha*G + (alpha-1)*S1 - S2 + b2)
    k_final<<<NN / 256, 256>>>(b2, out);
}